// round 10
// baseline (speedup 1.0000x reference)
#include <cuda_runtime.h>
#include <cuda_bf16.h>
#include <cstdint>

#define D_MODEL 256
#define MAXE 160000
#define MAXN 10240

typedef unsigned short ushort_t;

// ---------------- scratch (static device globals; no allocs allowed) ----------
__device__ float g_nQ1[MAXN * D_MODEL];
__device__ float g_nK1[MAXN * D_MODEL];
__device__ float g_nV1[MAXN * D_MODEL];
__device__ float g_nK2[MAXN * D_MODEL];
__device__ float g_nV2[MAXN * D_MODEL];
__device__ float g_e0[(size_t)MAXE * D_MODEL];
__device__ float g_e1[(size_t)MAXE * D_MODEL];
__device__ float g_alpha[MAXE];
__device__ float g_eexp[MAXE];
__device__ unsigned g_amax[MAXN];
__device__ float g_denom[MAXN];

// split-bf16 operand storage (hi/lo), 16B-aligned for cp.async
__device__ __align__(16) ushort_t g_xh[MAXN * D_MODEL];
__device__ __align__(16) ushort_t g_xl[MAXN * D_MODEL];
#define WPOOL 1507328
__device__ __align__(16) ushort_t g_wh[WPOOL];
__device__ __align__(16) ushort_t g_wl[WPOOL];
__device__ __align__(16) ushort_t g_pAh[(size_t)MAXE * D_MODEL];
__device__ __align__(16) ushort_t g_pAl[(size_t)MAXE * D_MODEL];
__device__ __align__(16) ushort_t g_pBh[(size_t)MAXE * D_MODEL];
__device__ __align__(16) ushort_t g_pBl[(size_t)MAXE * D_MODEL];
__device__ __align__(16) ushort_t g_b0h[(size_t)MAXE * 3 * D_MODEL];
__device__ __align__(16) ushort_t g_b0l[(size_t)MAXE * 3 * D_MODEL];
__device__ __align__(16) ushort_t g_b1h[(size_t)MAXE * 3 * D_MODEL];
__device__ __align__(16) ushort_t g_b1l[(size_t)MAXE * 3 * D_MODEL];

// ---------------- helpers ----------------------------------------------------
__device__ __forceinline__ float warp_sum(float v) {
    #pragma unroll
    for (int o = 16; o > 0; o >>= 1) v += __shfl_xor_sync(0xFFFFFFFFu, v, o);
    return v;
}
__device__ __forceinline__ unsigned fkey(float f) {
    unsigned u = __float_as_uint(f);
    return (u & 0x80000000u) ? ~u : (u | 0x80000000u);
}
__device__ __forceinline__ float funkey(unsigned k) {
    unsigned u = (k & 0x80000000u) ? (k & 0x7FFFFFFFu) : ~k;
    return __uint_as_float(u);
}
__device__ __forceinline__ void split1(float v, ushort_t& h, ushort_t& l) {
    unsigned u = __float_as_uint(v);
    h = (ushort_t)(u >> 16);
    float res = v - __uint_as_float(u & 0xFFFF0000u);
    l = __bfloat16_as_ushort(__float2bfloat16_rn(res));
}

__device__ __forceinline__ void mma16816(float* c, const unsigned* a, unsigned b0, unsigned b1) {
    asm volatile(
        "mma.sync.aligned.m16n8k16.row.col.f32.bf16.bf16.f32 "
        "{%0,%1,%2,%3}, {%4,%5,%6,%7}, {%8,%9}, {%0,%1,%2,%3};\n"
        : "+f"(c[0]), "+f"(c[1]), "+f"(c[2]), "+f"(c[3])
        : "r"(a[0]), "r"(a[1]), "r"(a[2]), "r"(a[3]), "r"(b0), "r"(b1));
}
__device__ __forceinline__ void ldsm_x4(unsigned& r0, unsigned& r1, unsigned& r2, unsigned& r3,
                                        uint32_t addr) {
    asm volatile("ldmatrix.sync.aligned.m8n8.x4.shared.b16 {%0,%1,%2,%3}, [%4];"
                 : "=r"(r0), "=r"(r1), "=r"(r2), "=r"(r3) : "r"(addr));
}
__device__ __forceinline__ uint32_t smem_u32(const void* p) {
    uint32_t a;
    asm("{ .reg .u64 t; cvta.to.shared.u64 t, %1; cvt.u32.u64 %0, t; }" : "=r"(a) : "l"(p));
    return a;
}
#define CP16(sdst, gsrc, n) \
    asm volatile("cp.async.cg.shared.global [%0], [%1], 16, %2;" :: "r"(sdst), "l"(gsrc), "r"(n))
#define CP_COMMIT() asm volatile("cp.async.commit_group;")
#define CP_WAIT1()  asm volatile("cp.async.wait_group 1;")
#define CP_WAIT0()  asm volatile("cp.async.wait_group 0;")

// ---------------- split conversion kernel -------------------------------------
__global__ void split_kernel(const float* __restrict__ src, ushort_t* __restrict__ hi,
                             ushort_t* __restrict__ lo, int n) {
    int i = blockIdx.x * blockDim.x + threadIdx.x;
    if (i < n) {
        ushort_t h, l;
        split1(src[i], h, l);
        hi[i] = h; lo[i] = l;
    }
}

// ---------------- HMMA GEMM (pre-split bf16, ldmatrix, 2 CTAs/SM) -------------
// C[M,N] = act(A[M,K] @ W[N,K]^T + bias[N]).
// 128x128 block tile, K-chunk 32, cp.async double buffer, 256 thr (8 warps 2Mx4N).
// 3 MMA passes: Ah*Wh + Al*Wh + Ah*Wl.
#define SROW 80                     // smem bytes per 32-bf16 row (64 data + 16 pad)
#define TILEB (128 * SROW)          // 10240 B
#define STAGEB (4 * TILEB)          // Ah, Al, Wh, Wl -> 40960 B
#define GSMEM (2 * STAGEB)          // 81920 B -> 2 CTAs/SM

template <int ACT, int OUTMODE>  // ACT: 0 none, 1 lrelu. OUTMODE: 0 fp32, 1 hilo
__global__ __launch_bounds__(256, 2)
void gemm_cp(const ushort_t* __restrict__ Ah, const ushort_t* __restrict__ Al,
             const ushort_t* __restrict__ Wh, const ushort_t* __restrict__ Wl,
             const float* __restrict__ bias, float* __restrict__ Cf,
             ushort_t* __restrict__ Chi, ushort_t* __restrict__ Clo,
             int M, int N, int K) {
    extern __shared__ char smem[];
    const uint32_t sb = smem_u32(smem);
    const int tid = threadIdx.x, wid = tid >> 5, lane = tid & 31;
    const int wm = wid & 1, wn = wid >> 1;
    const int g = lane >> 2, t = lane & 3;
    const int bm = blockIdx.y * 128, bn = blockIdx.x * 128;

    // cp.async mapping: 512 16B segs per tile; 2 per thread per tile
    const int crow0 = tid >> 2;          // f2 = tid + i*256 -> row = f2>>2
    const int cseg = tid & 3;

    auto issue = [&](int ch, int s) {
        const int k0 = ch << 5;
        const uint32_t so = (uint32_t)s * STAGEB;
        const ushort_t* bases[4] = {Ah, Al, Wh, Wl};
        #pragma unroll
        for (int tile = 0; tile < 4; tile++) {
            const int rb = (tile < 2) ? bm : bn;
            const ushort_t* base = bases[tile];
            #pragma unroll
            for (int i = 0; i < 2; i++) {
                int row = crow0 + i * 64;
                int gr = rb + row;
                int valid;
                if (tile < 2) { valid = (gr < M) ? 16 : 0; if (gr >= M) gr = M - 1; }
                else valid = 16;   // N multiple of 128
                const ushort_t* gp = base + (size_t)gr * K + k0 + cseg * 8;
                uint32_t sp = sb + so + (uint32_t)tile * TILEB + row * SROW + cseg * 16;
                CP16(sp, gp, valid);
            }
        }
    };

    // ldmatrix per-lane address components
    const int rowin = ((lane >> 3) & 1) * 8 + (lane & 7);
    const int kb = (lane >> 4) << 4;     // 0 or 16 bytes (k 0-7 / 8-15)

    float acc[4][4][4];
    #pragma unroll
    for (int i = 0; i < 4; i++)
        #pragma unroll
        for (int j = 0; j < 4; j++)
            #pragma unroll
            for (int r = 0; r < 4; r++) acc[i][j][r] = 0.f;

    const int nch = K >> 5;
    issue(0, 0);
    CP_COMMIT();

    for (int ch = 0; ch < nch; ch++) {
        const int s = ch & 1;
        if (ch + 1 < nch) { issue(ch + 1, (ch + 1) & 1); CP_COMMIT(); CP_WAIT1(); }
        else              { CP_WAIT0(); }
        __syncthreads();

        const uint32_t st = sb + (uint32_t)s * STAGEB;
        const uint32_t AhT = st;
        const uint32_t AlT = st + TILEB;
        const uint32_t WhT = st + 2 * TILEB;
        const uint32_t WlT = st + 3 * TILEB;

        #pragma unroll
        for (int ks = 0; ks < 32; ks += 16) {
            const uint32_t lko = (uint32_t)(ks * 2 + kb);
            // B fragments: 2 LDSM.x4 per precision (each covers two 8-wide nt tiles)
            unsigned bh[4][2], bl[4][2];
            #pragma unroll
            for (int p = 0; p < 2; p++) {
                uint32_t boff = (uint32_t)((wn * 32 + p * 16 + rowin) * SROW) + lko;
                ldsm_x4(bh[2 * p][0], bh[2 * p + 1][0], bh[2 * p][1], bh[2 * p + 1][1], WhT + boff);
                ldsm_x4(bl[2 * p][0], bl[2 * p + 1][0], bl[2 * p][1], bl[2 * p + 1][1], WlT + boff);
            }
            #pragma unroll
            for (int mt = 0; mt < 4; mt++) {
                uint32_t aoff = (uint32_t)((wm * 64 + mt * 16 + rowin) * SROW) + lko;
                unsigned ah[4], al[4];
                ldsm_x4(ah[0], ah[1], ah[2], ah[3], AhT + aoff);
                ldsm_x4(al[0], al[1], al[2], al[3], AlT + aoff);
                #pragma unroll
                for (int nt = 0; nt < 4; nt++) mma16816(acc[mt][nt], ah, bh[nt][0], bh[nt][1]);
                #pragma unroll
                for (int nt = 0; nt < 4; nt++) mma16816(acc[mt][nt], al, bh[nt][0], bh[nt][1]);
                #pragma unroll
                for (int nt = 0; nt < 4; nt++) mma16816(acc[mt][nt], ah, bl[nt][0], bl[nt][1]);
            }
        }
        __syncthreads();
    }

    // epilogue
    #pragma unroll
    for (int mt = 0; mt < 4; mt++) {
        #pragma unroll
        for (int nt = 0; nt < 4; nt++) {
            int r = bm + wm * 64 + mt * 16 + g;
            int c = bn + wn * 32 + nt * 8 + t * 2;
            float bi0 = __ldg(&bias[c]), bi1 = __ldg(&bias[c + 1]);
            #pragma unroll
            for (int half = 0; half < 2; half++) {
                int rr = r + half * 8;
                if (rr < M) {
                    float v0 = acc[mt][nt][half * 2 + 0] + bi0;
                    float v1 = acc[mt][nt][half * 2 + 1] + bi1;
                    if (ACT == 1) {
                        v0 = v0 > 0.f ? v0 : 0.2f * v0;
                        v1 = v1 > 0.f ? v1 : 0.2f * v1;
                    }
                    if (OUTMODE == 0) {
                        *(float2*)(Cf + (size_t)rr * N + c) = make_float2(v0, v1);
                    } else {
                        ushort_t h0, l0, h1, l1;
                        split1(v0, h0, l0);
                        split1(v1, h1, l1);
                        *(unsigned*)(Chi + (size_t)rr * N + c) = (unsigned)h0 | ((unsigned)h1 << 16);
                        *(unsigned*)(Clo + (size_t)rr * N + c) = (unsigned)l0 | ((unsigned)l1 << 16);
                    }
                }
            }
        }
    }
}

// ---------------- segment-softmax pieces --------------------------------------
__global__ void init_seg_kernel(unsigned* amax, float* denom, int n) {
    int i = blockIdx.x * blockDim.x + threadIdx.x;
    if (i < n) { amax[i] = 0u; denom[i] = 0.f; }
}

__global__ void alpha_kernel(const float* __restrict__ Q, const int* __restrict__ qidx,
                             const float* __restrict__ Kn,
                             const int* __restrict__ src, const int* __restrict__ dst,
                             float* __restrict__ alpha, unsigned* __restrict__ amax, int E) {
    int e = (blockIdx.x * blockDim.x + threadIdx.x) >> 5;
    int lane = threadIdx.x & 31;
    if (e >= E) return;
    const float* qr = Q + (size_t)(qidx ? qidx[e] : e) * D_MODEL;
    const float* kr = Kn + (size_t)src[e] * D_MODEL;
    float s = 0.f;
    #pragma unroll
    for (int i = 0; i < 8; i++) {
        int d = lane + 32 * i;
        s += qr[d] * kr[d];
    }
    s = warp_sum(s);
    if (lane == 0) {
        alpha[e] = s;
        atomicMax(&amax[dst[e]], fkey(s));
    }
}

__global__ void exp_denom_kernel(const float* __restrict__ alpha, const unsigned* __restrict__ amax,
                                 const int* __restrict__ dst,
                                 float* __restrict__ eexp, float* __restrict__ denom, int E) {
    int e = blockIdx.x * blockDim.x + threadIdx.x;
    if (e >= E) return;
    float m = funkey(amax[dst[e]]);
    float v = expf(alpha[e] - m);
    eexp[e] = v;
    atomicAdd(&denom[dst[e]], v);
}

__global__ void attn_ln_kernel(const float* __restrict__ Q, const int* __restrict__ qidx,
                               const float* __restrict__ Vn,
                               const int* __restrict__ src, const int* __restrict__ dst,
                               const float* __restrict__ eexp, const float* __restrict__ denom,
                               const float* __restrict__ g, const float* __restrict__ b,
                               ushort_t* __restrict__ oh, ushort_t* __restrict__ ol, int E) {
    int e = (blockIdx.x * blockDim.x + threadIdx.x) >> 5;
    int lane = threadIdx.x & 31;
    if (e >= E) return;
    const float* qr = Q + (size_t)(qidx ? qidx[e] : e) * D_MODEL;
    const float* vr = Vn + (size_t)src[e] * D_MODEL;
    float attn = eexp[e] / denom[dst[e]];
    float vals[8];
    #pragma unroll
    for (int i = 0; i < 8; i++) {
        int d = lane + 32 * i;
        vals[i] = qr[d] + attn * vr[d];
    }
    float s = 0.f;
    #pragma unroll
    for (int i = 0; i < 8; i++) s += vals[i];
    float mean = warp_sum(s) * (1.f / 256.f);
    float q2 = 0.f;
    #pragma unroll
    for (int i = 0; i < 8; i++) { float tt = vals[i] - mean; q2 += tt * tt; }
    float rstd = rsqrtf(warp_sum(q2) * (1.f / 256.f) + 1e-5f);
    #pragma unroll
    for (int i = 0; i < 8; i++) {
        int d = lane + 32 * i;
        float y = (vals[i] - mean) * rstd * g[d] + b[d];
        ushort_t h, l;
        split1(y, h, l);
        oh[(size_t)e * D_MODEL + d] = h;
        ol[(size_t)e * D_MODEL + d] = l;
    }
}

__global__ void lrelu_ln_kernel(const float* __restrict__ in,
                                const float* __restrict__ g, const float* __restrict__ b,
                                float* __restrict__ outf,
                                ushort_t* __restrict__ oh, ushort_t* __restrict__ ol, int E) {
    int e = (blockIdx.x * blockDim.x + threadIdx.x) >> 5;
    int lane = threadIdx.x & 31;
    if (e >= E) return;
    const float* ir = in + (size_t)e * D_MODEL;
    float vals[8];
    #pragma unroll
    for (int i = 0; i < 8; i++) {
        float v = ir[lane + 32 * i];
        vals[i] = v > 0.f ? v : 0.2f * v;
    }
    float s = 0.f;
    #pragma unroll
    for (int i = 0; i < 8; i++) s += vals[i];
    float mean = warp_sum(s) * (1.f / 256.f);
    float q2 = 0.f;
    #pragma unroll
    for (int i = 0; i < 8; i++) { float tt = vals[i] - mean; q2 += tt * tt; }
    float rstd = rsqrtf(warp_sum(q2) * (1.f / 256.f) + 1e-5f);
    #pragma unroll
    for (int i = 0; i < 8; i++) {
        int d = lane + 32 * i;
        float y = (vals[i] - mean) * rstd * g[d] + b[d];
        outf[(size_t)e * D_MODEL + d] = y;
        ushort_t h, l;
        split1(y, h, l);
        oh[(size_t)e * D_MODEL + d] = h;
        ol[(size_t)e * D_MODEL + d] = l;
    }
}

__global__ void final_kernel(const float* __restrict__ h3, const float* __restrict__ qf,
                             const float* __restrict__ g, const float* __restrict__ b,
                             const float* __restrict__ Wvec, const float* __restrict__ bvec,
                             float* __restrict__ out, int E) {
    int e = (blockIdx.x * blockDim.x + threadIdx.x) >> 5;
    int lane = threadIdx.x & 31;
    if (e >= E) return;
    const float* hr = h3 + (size_t)e * D_MODEL;
    const float* qr = qf + (size_t)e * D_MODEL;
    float vals[8];
    #pragma unroll
    for (int i = 0; i < 8; i++) {
        int d = lane + 32 * i;
        vals[i] = hr[d] + qr[d];
    }
    float s = 0.f;
    #pragma unroll
    for (int i = 0; i < 8; i++) s += vals[i];
    float mean = warp_sum(s) * (1.f / 256.f);
    float q2 = 0.f;
    #pragma unroll
    for (int i = 0; i < 8; i++) { float tt = vals[i] - mean; q2 += tt * tt; }
    float rstd = rsqrtf(warp_sum(q2) * (1.f / 256.f) + 1e-5f);
    float dotv = 0.f;
    #pragma unroll
    for (int i = 0; i < 8; i++) {
        int d = lane + 32 * i;
        float hn = (vals[i] - mean) * rstd * g[d] + b[d];
        dotv += hn * Wvec[d];
    }
    dotv = warp_sum(dotv);
    if (lane == 0) out[e] = dotv + bvec[0];
}

// ---------------- launch ------------------------------------------------------
extern "C" void kernel_launch(void* const* d_in, const int* in_sizes, int n_in,
                              void* d_out, int out_size) {
    const int*   ei   = (const int*)d_in[0];
    const float* x    = (const float*)d_in[1];
    const float* Wq   = (const float*)d_in[2];
    const float* bq   = (const float*)d_in[3];
    const float* Wk   = (const float*)d_in[4];
    const float* bk   = (const float*)d_in[5];
    const float* Wv   = (const float*)d_in[6];
    const float* bv   = (const float*)d_in[7];
    const float* Wff  = (const float*)d_in[8];
    const float* bff  = (const float*)d_in[9];
    const float* ga   = (const float*)d_in[10];
    const float* ba   = (const float*)d_in[11];
    const float* gf   = (const float*)d_in[12];
    const float* bf   = (const float*)d_in[13];
    const float* gfin = (const float*)d_in[14];
    const float* bfin = (const float*)d_in[15];
    const float* W3   = (const float*)d_in[16];
    const float* b3   = (const float*)d_in[17];
    const float* W4   = (const float*)d_in[18];
    const float* b4   = (const float*)d_in[19];
    const float* W5   = (const float*)d_in[20];
    const float* b5   = (const float*)d_in[21];
    const float* Wvec = (const float*)d_in[22];
    const float* bvec = (const float*)d_in[23];
    float* out = (float*)d_out;

    const int E  = in_sizes[0] / 2;
    const int Nn = in_sizes[1] / D_MODEL;
    const int D  = D_MODEL;
    const int DD = D * D;
    const int* src = ei;
    const int* dst = ei + E;

    float *nQ1, *nK1, *nV1, *nK2, *nV2, *e0f, *e1f, *alpha, *eexp, *denom;
    unsigned* amax;
    ushort_t *xh, *xl, *wh, *wl, *pAh, *pAl, *pBh, *pBl, *b0h, *b0l, *b1h, *b1l;
    cudaGetSymbolAddress((void**)&nQ1, g_nQ1);
    cudaGetSymbolAddress((void**)&nK1, g_nK1);
    cudaGetSymbolAddress((void**)&nV1, g_nV1);
    cudaGetSymbolAddress((void**)&nK2, g_nK2);
    cudaGetSymbolAddress((void**)&nV2, g_nV2);
    cudaGetSymbolAddress((void**)&e0f, g_e0);
    cudaGetSymbolAddress((void**)&e1f, g_e1);
    cudaGetSymbolAddress((void**)&alpha, g_alpha);
    cudaGetSymbolAddress((void**)&eexp, g_eexp);
    cudaGetSymbolAddress((void**)&amax, g_amax);
    cudaGetSymbolAddress((void**)&denom, g_denom);
    cudaGetSymbolAddress((void**)&xh, g_xh);
    cudaGetSymbolAddress((void**)&xl, g_xl);
    cudaGetSymbolAddress((void**)&wh, g_wh);
    cudaGetSymbolAddress((void**)&wl, g_wl);
    cudaGetSymbolAddress((void**)&pAh, g_pAh);
    cudaGetSymbolAddress((void**)&pAl, g_pAl);
    cudaGetSymbolAddress((void**)&pBh, g_pBh);
    cudaGetSymbolAddress((void**)&pBl, g_pBl);
    cudaGetSymbolAddress((void**)&b0h, g_b0h);
    cudaGetSymbolAddress((void**)&b0l, g_b0l);
    cudaGetSymbolAddress((void**)&b1h, g_b1h);
    cudaGetSymbolAddress((void**)&b1l, g_b1l);

    const int oQ = 0, oK = 2 * DD, oV = 4 * DD, oFF = 6 * DD;
    const int o3 = 8 * DD, o4 = o3 + 3 * DD, o5 = o4 + 9 * DD;

    cudaFuncSetAttribute(gemm_cp<0,0>, cudaFuncAttributeMaxDynamicSharedMemorySize, GSMEM);
    cudaFuncSetAttribute(gemm_cp<0,1>, cudaFuncAttributeMaxDynamicSharedMemorySize, GSMEM);
    cudaFuncSetAttribute(gemm_cp<1,1>, cudaFuncAttributeMaxDynamicSharedMemorySize, GSMEM);

    auto conv = [&](const float* s, ushort_t* h, ushort_t* l, int n) {
        split_kernel<<<(n + 255) / 256, 256>>>(s, h, l, n);
    };
    conv(x,   xh,      xl,      Nn * D);
    conv(Wq,  wh + oQ,  wl + oQ,  2 * DD);
    conv(Wk,  wh + oK,  wl + oK,  2 * DD);
    conv(Wv,  wh + oV,  wl + oV,  2 * DD);
    conv(Wff, wh + oFF, wl + oFF, 2 * DD);
    conv(W3,  wh + o3,  wl + o3,  3 * DD);
    conv(W4,  wh + o4,  wl + o4,  9 * DD);
    conv(W5,  wh + o5,  wl + o5,  3 * DD);

    dim3 gNode(2, (Nn + 127) / 128);
    dim3 gEdgeD(2, (E + 127) / 128);
    dim3 gEdge3D(6, (E + 127) / 128);
    const int warpBlocks = (E * 32 + 255) / 256;
    const int thrBlocks = (E + 255) / 256;
    const int segBlocks = (Nn + 255) / 256;

    // node-level projections
    gemm_cp<0,0><<<gNode, 256, GSMEM>>>(xh, xl, wh + oQ,      wl + oQ,      bq,     nQ1, 0, 0, Nn, D, D);
    gemm_cp<0,0><<<gNode, 256, GSMEM>>>(xh, xl, wh + oK,      wl + oK,      bk,     nK1, 0, 0, Nn, D, D);
    gemm_cp<0,0><<<gNode, 256, GSMEM>>>(xh, xl, wh + oV,      wl + oV,      bv,     nV1, 0, 0, Nn, D, D);
    gemm_cp<0,0><<<gNode, 256, GSMEM>>>(xh, xl, wh + oK + DD, wl + oK + DD, bk + D, nK2, 0, 0, Nn, D, D);
    gemm_cp<0,0><<<gNode, 256, GSMEM>>>(xh, xl, wh + oV + DD, wl + oV + DD, bv + D, nV2, 0, 0, Nn, D, D);

    // ---- layer 1 ----
    init_seg_kernel<<<segBlocks, 256>>>(amax, denom, Nn);
    alpha_kernel<<<warpBlocks, 256>>>(nQ1, dst, nK1, src, dst, alpha, amax, E);
    exp_denom_kernel<<<thrBlocks, 256>>>(alpha, amax, dst, eexp, denom, E);
    attn_ln_kernel<<<warpBlocks, 256>>>(nQ1, dst, nV1, src, dst, eexp, denom, ga, ba, pAh, pAl, E);
    gemm_cp<0,1><<<gEdgeD, 256, GSMEM>>>(pAh, pAl, wh + oFF, wl + oFF, bff, 0, pBh, pBl, E, D, D);

    // ---- layer 2 ----
    gemm_cp<0,0><<<gEdgeD, 256, GSMEM>>>(pBh, pBl, wh + oQ + DD, wl + oQ + DD, bq + D, e0f, 0, 0, E, D, D);
    init_seg_kernel<<<segBlocks, 256>>>(amax, denom, Nn);
    alpha_kernel<<<warpBlocks, 256>>>(e0f, nullptr, nK2, src, dst, alpha, amax, E);
    exp_denom_kernel<<<thrBlocks, 256>>>(alpha, amax, dst, eexp, denom, E);
    attn_ln_kernel<<<warpBlocks, 256>>>(e0f, nullptr, nV2, src, dst, eexp, denom, ga + D, ba + D, pAh, pAl, E);
    gemm_cp<0,0><<<gEdgeD, 256, GSMEM>>>(pAh, pAl, wh + oFF + DD, wl + oFF + DD, bff + D, e0f, 0, 0, E, D, D);

    // ---- head ----
    lrelu_ln_kernel<<<warpBlocks, 256>>>(e0f, gf, bf, e1f, pBh, pBl, E);
    gemm_cp<1,1><<<gEdge3D, 256, GSMEM>>>(pBh, pBl, wh + o3, wl + o3, b3, 0, b0h, b0l, E, 3 * D, D);
    gemm_cp<1,1><<<gEdge3D, 256, GSMEM>>>(b0h, b0l, wh + o4, wl + o4, b4, 0, b1h, b1l, E, 3 * D, 3 * D);
    gemm_cp<0,0><<<gEdgeD, 256, GSMEM>>>(b1h, b1l, wh + o5, wl + o5, b5, e0f, 0, 0, E, D, 3 * D);
    final_kernel<<<warpBlocks, 256>>>(e0f, e1f, gfin, bfin, Wvec, bvec, out, E);

    (void)n_in; (void)out_size;
}

// round 16
// speedup vs baseline: 1.0654x; 1.0654x over previous
#include <cuda_runtime.h>
#include <cuda_bf16.h>
#include <cstdint>

#define D_MODEL 256
#define MAXE 160000
#define MAXN 10240

typedef unsigned short ushort_t;

// ---------------- scratch (static device globals; no allocs allowed) ----------
__device__ float g_nQ1[MAXN * D_MODEL];
__device__ float g_nK1[MAXN * D_MODEL];
__device__ float g_nV1[MAXN * D_MODEL];
__device__ float g_nK2[MAXN * D_MODEL];
__device__ float g_nV2[MAXN * D_MODEL];
__device__ float g_e0[(size_t)MAXE * D_MODEL];
__device__ float g_e1[(size_t)MAXE * D_MODEL];
__device__ float g_alpha[MAXE];
__device__ float g_eexp[MAXE];
__device__ unsigned g_amax[MAXN];
__device__ float g_denom[MAXN];

// split-bf16 operand storage (hi/lo), 16B-aligned for cp.async
__device__ __align__(16) ushort_t g_xh[MAXN * D_MODEL];
__device__ __align__(16) ushort_t g_xl[MAXN * D_MODEL];
#define WPOOL 1507328
__device__ __align__(16) ushort_t g_wh[WPOOL];
__device__ __align__(16) ushort_t g_wl[WPOOL];
__device__ __align__(16) ushort_t g_pAh[(size_t)MAXE * D_MODEL];
__device__ __align__(16) ushort_t g_pAl[(size_t)MAXE * D_MODEL];
__device__ __align__(16) ushort_t g_pBh[(size_t)MAXE * D_MODEL];
__device__ __align__(16) ushort_t g_pBl[(size_t)MAXE * D_MODEL];
__device__ __align__(16) ushort_t g_b0h[(size_t)MAXE * 3 * D_MODEL];
__device__ __align__(16) ushort_t g_b0l[(size_t)MAXE * 3 * D_MODEL];
__device__ __align__(16) ushort_t g_b1h[(size_t)MAXE * 3 * D_MODEL];
__device__ __align__(16) ushort_t g_b1l[(size_t)MAXE * 3 * D_MODEL];

// ---------------- helpers ----------------------------------------------------
__device__ __forceinline__ float warp_sum(float v) {
    #pragma unroll
    for (int o = 16; o > 0; o >>= 1) v += __shfl_xor_sync(0xFFFFFFFFu, v, o);
    return v;
}
__device__ __forceinline__ unsigned fkey(float f) {
    unsigned u = __float_as_uint(f);
    return (u & 0x80000000u) ? ~u : (u | 0x80000000u);
}
__device__ __forceinline__ float funkey(unsigned k) {
    unsigned u = (k & 0x80000000u) ? (k & 0x7FFFFFFFu) : ~k;
    return __uint_as_float(u);
}
__device__ __forceinline__ void split1(float v, ushort_t& h, ushort_t& l) {
    unsigned u = __float_as_uint(v);
    h = (ushort_t)(u >> 16);
    float res = v - __uint_as_float(u & 0xFFFF0000u);
    l = __bfloat16_as_ushort(__float2bfloat16_rn(res));
}

__device__ __forceinline__ void mma16816(float* c, const unsigned* a, unsigned b0, unsigned b1) {
    asm volatile(
        "mma.sync.aligned.m16n8k16.row.col.f32.bf16.bf16.f32 "
        "{%0,%1,%2,%3}, {%4,%5,%6,%7}, {%8,%9}, {%0,%1,%2,%3};\n"
        : "+f"(c[0]), "+f"(c[1]), "+f"(c[2]), "+f"(c[3])
        : "r"(a[0]), "r"(a[1]), "r"(a[2]), "r"(a[3]), "r"(b0), "r"(b1));
}
__device__ __forceinline__ uint32_t smem_u32(const void* p) {
    uint32_t a;
    asm("{ .reg .u64 t; cvta.to.shared.u64 t, %1; cvt.u32.u64 %0, t; }" : "=r"(a) : "l"(p));
    return a;
}
#define CP16(sdst, gsrc, n) \
    asm volatile("cp.async.cg.shared.global [%0], [%1], 16, %2;" :: "r"(sdst), "l"(gsrc), "r"(n))
#define CP_COMMIT() asm volatile("cp.async.commit_group;")
#define CP_WAIT1()  asm volatile("cp.async.wait_group 1;")
#define CP_WAIT0()  asm volatile("cp.async.wait_group 0;")

// ---------------- split conversion kernel -------------------------------------
__global__ void split_kernel(const float* __restrict__ src, ushort_t* __restrict__ hi,
                             ushort_t* __restrict__ lo, int n) {
    int i = blockIdx.x * blockDim.x + threadIdx.x;
    if (i < n) {
        ushort_t h, l;
        split1(src[i], h, l);
        hi[i] = h; lo[i] = l;
    }
}

// ---------------- HMMA GEMM (pre-split bf16, cp.async, 256x128 tile) ----------
// C[M,N] = act(A[M,K] @ W[N,K]^T + bias[N]); 3 passes: Ah*Wh + Al*Wh + Ah*Wl.
// Block tile 256x128, K-chunk 64, cp.async double buffer, 512 thr (16 warps 4Mx4N).
// Warp tile 64x32 (identical inner loop to the proven 3895us kernel).
#define SPADB 144                    // smem bytes per 64-bf16 row (128 data + 16 pad)
#define ATILEB (256 * SPADB)         // 36864 B
#define WTILEB (128 * SPADB)         // 18432 B
#define STAGEB (2 * ATILEB + 2 * WTILEB)   // 110592 B
#define GSMEM (2 * STAGEB)           // 221184 B

template <int ACT, int OUTMODE>  // ACT: 0 none, 1 lrelu. OUTMODE: 0 fp32, 1 hilo
__global__ __launch_bounds__(512)
void gemm_cp(const ushort_t* __restrict__ Ah, const ushort_t* __restrict__ Al,
             const ushort_t* __restrict__ Wh, const ushort_t* __restrict__ Wl,
             const float* __restrict__ bias, float* __restrict__ Cf,
             ushort_t* __restrict__ Chi, ushort_t* __restrict__ Clo,
             int M, int N, int K) {
    extern __shared__ char smem[];
    const uint32_t sb = smem_u32(smem);
    const int tid = threadIdx.x, wid = tid >> 5, lane = tid & 31;
    const int wm = wid & 3, wn = wid >> 2;     // 4M x 4N warps
    const int g = lane >> 2, t = lane & 3;
    const int bm = blockIdx.y * 256, bn = blockIdx.x * 128;

    // cp.async mapping: 512 threads; A tiles 2048 segs (4/thr), W tiles 1024 (2/thr)
    const int crow = tid >> 3;          // 0..63
    const int cch = tid & 7;            // 16B seg within 128B row

    auto issue = [&](int ch, int s) {
        const int k0 = ch << 6;
        const uint32_t so = (uint32_t)s * STAGEB;
        // A tiles (256 rows each): hi then lo
        #pragma unroll
        for (int tile = 0; tile < 2; tile++) {
            const ushort_t* base = tile ? Al : Ah;
            #pragma unroll
            for (int i = 0; i < 4; i++) {
                int row = crow + i * 64;
                int gr = bm + row;
                int valid = (gr < M) ? 16 : 0;
                if (gr >= M) gr = M - 1;
                const ushort_t* gp = base + (size_t)gr * K + k0 + cch * 8;
                uint32_t sp = sb + so + (uint32_t)tile * ATILEB + row * SPADB + cch * 16;
                CP16(sp, gp, valid);
            }
        }
        // W tiles (128 rows each): hi then lo; N always multiple of 128
        #pragma unroll
        for (int tile = 0; tile < 2; tile++) {
            const ushort_t* base = tile ? Wl : Wh;
            #pragma unroll
            for (int i = 0; i < 2; i++) {
                int row = crow + i * 64;
                int gr = bn + row;
                const ushort_t* gp = base + (size_t)gr * K + k0 + cch * 8;
                uint32_t sp = sb + so + 2 * ATILEB + (uint32_t)tile * WTILEB + row * SPADB + cch * 16;
                CP16(sp, gp, 16);
            }
        }
    };

    float acc[4][4][4];
    #pragma unroll
    for (int i = 0; i < 4; i++)
        #pragma unroll
        for (int j = 0; j < 4; j++)
            #pragma unroll
            for (int r = 0; r < 4; r++) acc[i][j][r] = 0.f;

    const int nch = K >> 6;
    issue(0, 0);
    CP_COMMIT();

    for (int ch = 0; ch < nch; ch++) {
        const int s = ch & 1;
        if (ch + 1 < nch) { issue(ch + 1, (ch + 1) & 1); CP_COMMIT(); CP_WAIT1(); }
        else              { CP_WAIT0(); }
        __syncthreads();

        const char* Ahs = smem + (size_t)s * STAGEB;
        const char* Als = Ahs + ATILEB;
        const char* Whs = Als + ATILEB;
        const char* Wls = Whs + WTILEB;

        #pragma unroll
        for (int ks = 0; ks < 64; ks += 16) {
            const int cb = ks * 2 + t * 4;   // byte offset of k-pair within row
            unsigned bh[4][2], bl[4][2];
            #pragma unroll
            for (int nt = 0; nt < 4; nt++) {
                int n0 = wn * 32 + nt * 8 + g;
                bh[nt][0] = *(const unsigned*)(Whs + n0 * SPADB + cb);
                bh[nt][1] = *(const unsigned*)(Whs + n0 * SPADB + cb + 16);
                bl[nt][0] = *(const unsigned*)(Wls + n0 * SPADB + cb);
                bl[nt][1] = *(const unsigned*)(Wls + n0 * SPADB + cb + 16);
            }
            #pragma unroll
            for (int mt = 0; mt < 4; mt++) {
                int r0 = wm * 64 + mt * 16 + g;
                unsigned ah[4], al[4];
                ah[0] = *(const unsigned*)(Ahs + r0 * SPADB + cb);
                ah[1] = *(const unsigned*)(Ahs + (r0 + 8) * SPADB + cb);
                ah[2] = *(const unsigned*)(Ahs + r0 * SPADB + cb + 16);
                ah[3] = *(const unsigned*)(Ahs + (r0 + 8) * SPADB + cb + 16);
                al[0] = *(const unsigned*)(Als + r0 * SPADB + cb);
                al[1] = *(const unsigned*)(Als + (r0 + 8) * SPADB + cb);
                al[2] = *(const unsigned*)(Als + r0 * SPADB + cb + 16);
                al[3] = *(const unsigned*)(Als + (r0 + 8) * SPADB + cb + 16);
                // pass-major within mt: same-acc deps separated by 4 MMAs
                #pragma unroll
                for (int nt = 0; nt < 4; nt++) mma16816(acc[mt][nt], ah, bh[nt][0], bh[nt][1]);
                #pragma unroll
                for (int nt = 0; nt < 4; nt++) mma16816(acc[mt][nt], al, bh[nt][0], bh[nt][1]);
                #pragma unroll
                for (int nt = 0; nt < 4; nt++) mma16816(acc[mt][nt], ah, bl[nt][0], bl[nt][1]);
            }
        }
        __syncthreads();
    }

    // epilogue
    #pragma unroll
    for (int mt = 0; mt < 4; mt++) {
        #pragma unroll
        for (int nt = 0; nt < 4; nt++) {
            int r = bm + wm * 64 + mt * 16 + g;
            int c = bn + wn * 32 + nt * 8 + t * 2;
            float bi0 = __ldg(&bias[c]), bi1 = __ldg(&bias[c + 1]);
            #pragma unroll
            for (int half = 0; half < 2; half++) {
                int rr = r + half * 8;
                if (rr < M) {
                    float v0 = acc[mt][nt][half * 2 + 0] + bi0;
                    float v1 = acc[mt][nt][half * 2 + 1] + bi1;
                    if (ACT == 1) {
                        v0 = v0 > 0.f ? v0 : 0.2f * v0;
                        v1 = v1 > 0.f ? v1 : 0.2f * v1;
                    }
                    if (OUTMODE == 0) {
                        *(float2*)(Cf + (size_t)rr * N + c) = make_float2(v0, v1);
                    } else {
                        ushort_t h0, l0, h1, l1;
                        split1(v0, h0, l0);
                        split1(v1, h1, l1);
                        *(unsigned*)(Chi + (size_t)rr * N + c) = (unsigned)h0 | ((unsigned)h1 << 16);
                        *(unsigned*)(Clo + (size_t)rr * N + c) = (unsigned)l0 | ((unsigned)l1 << 16);
                    }
                }
            }
        }
    }
}

// ---------------- segment-softmax pieces --------------------------------------
__global__ void init_seg_kernel(unsigned* amax, float* denom, int n) {
    int i = blockIdx.x * blockDim.x + threadIdx.x;
    if (i < n) { amax[i] = 0u; denom[i] = 0.f; }
}

__global__ void alpha_kernel(const float* __restrict__ Q, const int* __restrict__ qidx,
                             const float* __restrict__ Kn,
                             const int* __restrict__ src, const int* __restrict__ dst,
                             float* __restrict__ alpha, unsigned* __restrict__ amax, int E) {
    int e = (blockIdx.x * blockDim.x + threadIdx.x) >> 5;
    int lane = threadIdx.x & 31;
    if (e >= E) return;
    const float* qr = Q + (size_t)(qidx ? qidx[e] : e) * D_MODEL;
    const float* kr = Kn + (size_t)src[e] * D_MODEL;
    float s = 0.f;
    #pragma unroll
    for (int i = 0; i < 8; i++) {
        int d = lane + 32 * i;
        s += qr[d] * kr[d];
    }
    s = warp_sum(s);
    if (lane == 0) {
        alpha[e] = s;
        atomicMax(&amax[dst[e]], fkey(s));
    }
}

__global__ void exp_denom_kernel(const float* __restrict__ alpha, const unsigned* __restrict__ amax,
                                 const int* __restrict__ dst,
                                 float* __restrict__ eexp, float* __restrict__ denom, int E) {
    int e = blockIdx.x * blockDim.x + threadIdx.x;
    if (e >= E) return;
    float m = funkey(amax[dst[e]]);
    float v = expf(alpha[e] - m);
    eexp[e] = v;
    atomicAdd(&denom[dst[e]], v);
}

__global__ void attn_ln_kernel(const float* __restrict__ Q, const int* __restrict__ qidx,
                               const float* __restrict__ Vn,
                               const int* __restrict__ src, const int* __restrict__ dst,
                               const float* __restrict__ eexp, const float* __restrict__ denom,
                               const float* __restrict__ g, const float* __restrict__ b,
                               ushort_t* __restrict__ oh, ushort_t* __restrict__ ol, int E) {
    int e = (blockIdx.x * blockDim.x + threadIdx.x) >> 5;
    int lane = threadIdx.x & 31;
    if (e >= E) return;
    const float* qr = Q + (size_t)(qidx ? qidx[e] : e) * D_MODEL;
    const float* vr = Vn + (size_t)src[e] * D_MODEL;
    float attn = eexp[e] / denom[dst[e]];
    float vals[8];
    #pragma unroll
    for (int i = 0; i < 8; i++) {
        int d = lane + 32 * i;
        vals[i] = qr[d] + attn * vr[d];
    }
    float s = 0.f;
    #pragma unroll
    for (int i = 0; i < 8; i++) s += vals[i];
    float mean = warp_sum(s) * (1.f / 256.f);
    float q2 = 0.f;
    #pragma unroll
    for (int i = 0; i < 8; i++) { float tt = vals[i] - mean; q2 += tt * tt; }
    float rstd = rsqrtf(warp_sum(q2) * (1.f / 256.f) + 1e-5f);
    #pragma unroll
    for (int i = 0; i < 8; i++) {
        int d = lane + 32 * i;
        float y = (vals[i] - mean) * rstd * g[d] + b[d];
        ushort_t h, l;
        split1(y, h, l);
        oh[(size_t)e * D_MODEL + d] = h;
        ol[(size_t)e * D_MODEL + d] = l;
    }
}

__global__ void lrelu_ln_kernel(const float* __restrict__ in,
                                const float* __restrict__ g, const float* __restrict__ b,
                                float* __restrict__ outf,
                                ushort_t* __restrict__ oh, ushort_t* __restrict__ ol, int E) {
    int e = (blockIdx.x * blockDim.x + threadIdx.x) >> 5;
    int lane = threadIdx.x & 31;
    if (e >= E) return;
    const float* ir = in + (size_t)e * D_MODEL;
    float vals[8];
    #pragma unroll
    for (int i = 0; i < 8; i++) {
        float v = ir[lane + 32 * i];
        vals[i] = v > 0.f ? v : 0.2f * v;
    }
    float s = 0.f;
    #pragma unroll
    for (int i = 0; i < 8; i++) s += vals[i];
    float mean = warp_sum(s) * (1.f / 256.f);
    float q2 = 0.f;
    #pragma unroll
    for (int i = 0; i < 8; i++) { float tt = vals[i] - mean; q2 += tt * tt; }
    float rstd = rsqrtf(warp_sum(q2) * (1.f / 256.f) + 1e-5f);
    #pragma unroll
    for (int i = 0; i < 8; i++) {
        int d = lane + 32 * i;
        float y = (vals[i] - mean) * rstd * g[d] + b[d];
        outf[(size_t)e * D_MODEL + d] = y;
        ushort_t h, l;
        split1(y, h, l);
        oh[(size_t)e * D_MODEL + d] = h;
        ol[(size_t)e * D_MODEL + d] = l;
    }
}

__global__ void final_kernel(const float* __restrict__ h3, const float* __restrict__ qf,
                             const float* __restrict__ g, const float* __restrict__ b,
                             const float* __restrict__ Wvec, const float* __restrict__ bvec,
                             float* __restrict__ out, int E) {
    int e = (blockIdx.x * blockDim.x + threadIdx.x) >> 5;
    int lane = threadIdx.x & 31;
    if (e >= E) return;
    const float* hr = h3 + (size_t)e * D_MODEL;
    const float* qr = qf + (size_t)e * D_MODEL;
    float vals[8];
    #pragma unroll
    for (int i = 0; i < 8; i++) {
        int d = lane + 32 * i;
        vals[i] = hr[d] + qr[d];
    }
    float s = 0.f;
    #pragma unroll
    for (int i = 0; i < 8; i++) s += vals[i];
    float mean = warp_sum(s) * (1.f / 256.f);
    float q2 = 0.f;
    #pragma unroll
    for (int i = 0; i < 8; i++) { float tt = vals[i] - mean; q2 += tt * tt; }
    float rstd = rsqrtf(warp_sum(q2) * (1.f / 256.f) + 1e-5f);
    float dotv = 0.f;
    #pragma unroll
    for (int i = 0; i < 8; i++) {
        int d = lane + 32 * i;
        float hn = (vals[i] - mean) * rstd * g[d] + b[d];
        dotv += hn * Wvec[d];
    }
    dotv = warp_sum(dotv);
    if (lane == 0) out[e] = dotv + bvec[0];
}

// ---------------- launch ------------------------------------------------------
extern "C" void kernel_launch(void* const* d_in, const int* in_sizes, int n_in,
                              void* d_out, int out_size) {
    const int*   ei   = (const int*)d_in[0];
    const float* x    = (const float*)d_in[1];
    const float* Wq   = (const float*)d_in[2];
    const float* bq   = (const float*)d_in[3];
    const float* Wk   = (const float*)d_in[4];
    const float* bk   = (const float*)d_in[5];
    const float* Wv   = (const float*)d_in[6];
    const float* bv   = (const float*)d_in[7];
    const float* Wff  = (const float*)d_in[8];
    const float* bff  = (const float*)d_in[9];
    const float* ga   = (const float*)d_in[10];
    const float* ba   = (const float*)d_in[11];
    const float* gf   = (const float*)d_in[12];
    const float* bf   = (const float*)d_in[13];
    const float* gfin = (const float*)d_in[14];
    const float* bfin = (const float*)d_in[15];
    const float* W3   = (const float*)d_in[16];
    const float* b3   = (const float*)d_in[17];
    const float* W4   = (const float*)d_in[18];
    const float* b4   = (const float*)d_in[19];
    const float* W5   = (const float*)d_in[20];
    const float* b5   = (const float*)d_in[21];
    const float* Wvec = (const float*)d_in[22];
    const float* bvec = (const float*)d_in[23];
    float* out = (float*)d_out;

    const int E  = in_sizes[0] / 2;
    const int Nn = in_sizes[1] / D_MODEL;
    const int D  = D_MODEL;
    const int DD = D * D;
    const int* src = ei;
    const int* dst = ei + E;

    float *nQ1, *nK1, *nV1, *nK2, *nV2, *e0f, *e1f, *alpha, *eexp, *denom;
    unsigned* amax;
    ushort_t *xh, *xl, *wh, *wl, *pAh, *pAl, *pBh, *pBl, *b0h, *b0l, *b1h, *b1l;
    cudaGetSymbolAddress((void**)&nQ1, g_nQ1);
    cudaGetSymbolAddress((void**)&nK1, g_nK1);
    cudaGetSymbolAddress((void**)&nV1, g_nV1);
    cudaGetSymbolAddress((void**)&nK2, g_nK2);
    cudaGetSymbolAddress((void**)&nV2, g_nV2);
    cudaGetSymbolAddress((void**)&e0f, g_e0);
    cudaGetSymbolAddress((void**)&e1f, g_e1);
    cudaGetSymbolAddress((void**)&alpha, g_alpha);
    cudaGetSymbolAddress((void**)&eexp, g_eexp);
    cudaGetSymbolAddress((void**)&amax, g_amax);
    cudaGetSymbolAddress((void**)&denom, g_denom);
    cudaGetSymbolAddress((void**)&xh, g_xh);
    cudaGetSymbolAddress((void**)&xl, g_xl);
    cudaGetSymbolAddress((void**)&wh, g_wh);
    cudaGetSymbolAddress((void**)&wl, g_wl);
    cudaGetSymbolAddress((void**)&pAh, g_pAh);
    cudaGetSymbolAddress((void**)&pAl, g_pAl);
    cudaGetSymbolAddress((void**)&pBh, g_pBh);
    cudaGetSymbolAddress((void**)&pBl, g_pBl);
    cudaGetSymbolAddress((void**)&b0h, g_b0h);
    cudaGetSymbolAddress((void**)&b0l, g_b0l);
    cudaGetSymbolAddress((void**)&b1h, g_b1h);
    cudaGetSymbolAddress((void**)&b1l, g_b1l);

    const int oQ = 0, oK = 2 * DD, oV = 4 * DD, oFF = 6 * DD;
    const int o3 = 8 * DD, o4 = o3 + 3 * DD, o5 = o4 + 9 * DD;

    cudaFuncSetAttribute(gemm_cp<0,0>, cudaFuncAttributeMaxDynamicSharedMemorySize, GSMEM);
    cudaFuncSetAttribute(gemm_cp<0,1>, cudaFuncAttributeMaxDynamicSharedMemorySize, GSMEM);
    cudaFuncSetAttribute(gemm_cp<1,1>, cudaFuncAttributeMaxDynamicSharedMemorySize, GSMEM);

    auto conv = [&](const float* s, ushort_t* h, ushort_t* l, int n) {
        split_kernel<<<(n + 255) / 256, 256>>>(s, h, l, n);
    };
    conv(x,   xh,      xl,      Nn * D);
    conv(Wq,  wh + oQ,  wl + oQ,  2 * DD);
    conv(Wk,  wh + oK,  wl + oK,  2 * DD);
    conv(Wv,  wh + oV,  wl + oV,  2 * DD);
    conv(Wff, wh + oFF, wl + oFF, 2 * DD);
    conv(W3,  wh + o3,  wl + o3,  3 * DD);
    conv(W4,  wh + o4,  wl + o4,  9 * DD);
    conv(W5,  wh + o5,  wl + o5,  3 * DD);

    dim3 gNode(2, (Nn + 255) / 256);
    dim3 gEdgeD(2, (E + 255) / 256);
    dim3 gEdge3D(6, (E + 255) / 256);
    const int warpBlocks = (E * 32 + 255) / 256;
    const int thrBlocks = (E + 255) / 256;
    const int segBlocks = (Nn + 255) / 256;

    // node-level projections (full 3-pass precision)
    gemm_cp<0,0><<<gNode, 512, GSMEM>>>(xh, xl, wh + oQ,      wl + oQ,      bq,     nQ1, 0, 0, Nn, D, D);
    gemm_cp<0,0><<<gNode, 512, GSMEM>>>(xh, xl, wh + oK,      wl + oK,      bk,     nK1, 0, 0, Nn, D, D);
    gemm_cp<0,0><<<gNode, 512, GSMEM>>>(xh, xl, wh + oV,      wl + oV,      bv,     nV1, 0, 0, Nn, D, D);
    gemm_cp<0,0><<<gNode, 512, GSMEM>>>(xh, xl, wh + oK + DD, wl + oK + DD, bk + D, nK2, 0, 0, Nn, D, D);
    gemm_cp<0,0><<<gNode, 512, GSMEM>>>(xh, xl, wh + oV + DD, wl + oV + DD, bv + D, nV2, 0, 0, Nn, D, D);

    // ---- layer 1 ----
    init_seg_kernel<<<segBlocks, 256>>>(amax, denom, Nn);
    alpha_kernel<<<warpBlocks, 256>>>(nQ1, dst, nK1, src, dst, alpha, amax, E);
    exp_denom_kernel<<<thrBlocks, 256>>>(alpha, amax, dst, eexp, denom, E);
    attn_ln_kernel<<<warpBlocks, 256>>>(nQ1, dst, nV1, src, dst, eexp, denom, ga, ba, pAh, pAl, E);
    gemm_cp<0,1><<<gEdgeD, 512, GSMEM>>>(pAh, pAl, wh + oFF, wl + oFF, bff, 0, pBh, pBl, E, D, D);

    // ---- layer 2 ----
    gemm_cp<0,0><<<gEdgeD, 512, GSMEM>>>(pBh, pBl, wh + oQ + DD, wl + oQ + DD, bq + D, e0f, 0, 0, E, D, D);
    init_seg_kernel<<<segBlocks, 256>>>(amax, denom, Nn);
    alpha_kernel<<<warpBlocks, 256>>>(e0f, nullptr, nK2, src, dst, alpha, amax, E);
    exp_denom_kernel<<<thrBlocks, 256>>>(alpha, amax, dst, eexp, denom, E);
    attn_ln_kernel<<<warpBlocks, 256>>>(e0f, nullptr, nV2, src, dst, eexp, denom, ga + D, ba + D, pAh, pAl, E);
    gemm_cp<0,0><<<gEdgeD, 512, GSMEM>>>(pAh, pAl, wh + oFF + DD, wl + oFF + DD, bff + D, e0f, 0, 0, E, D, D);

    // ---- head (full 3-pass precision) ----
    lrelu_ln_kernel<<<warpBlocks, 256>>>(e0f, gf, bf, e1f, pBh, pBl, E);
    gemm_cp<1,1><<<gEdge3D, 512, GSMEM>>>(pBh, pBl, wh + o3, wl + o3, b3, 0, b0h, b0l, E, 3 * D, D);
    gemm_cp<1,1><<<gEdge3D, 512, GSMEM>>>(b0h, b0l, wh + o4, wl + o4, b4, 0, b1h, b1l, E, 3 * D, 3 * D);
    gemm_cp<0,0><<<gEdgeD, 512, GSMEM>>>(b1h, b1l, wh + o5, wl + o5, b5, e0f, 0, 0, E, D, 3 * D);
    final_kernel<<<warpBlocks, 256>>>(e0f, e1f, gfin, bfin, Wvec, bvec, out, E);

    (void)n_in; (void)out_size;
}